// round 12
// baseline (speedup 1.0000x reference)
#include <cuda_runtime.h>

// RAE GRU enc-dec. K0: pad+transpose Wih. K1: precompute all encoder gi.
// K2 (fused): encoder + decoder recurrences in ONE persistent kernel.
//   256 thr/CTA, 8 batch rows/thread, 2 teams with named barriers.
//   h kept in smem for cross-thread reads + own column in registers.
//   Decoder folds lin_W into the recurrent GEMM (out write is free).

typedef unsigned long long u64;

__device__ __forceinline__ u64 pk2(float lo, float hi) {
    u64 r; asm("mov.b64 %0, {%1,%2};" : "=l"(r) : "f"(lo), "f"(hi)); return r;
}
__device__ __forceinline__ float red2(u64 v) {
    float lo, hi; asm("mov.b64 {%0,%1}, %2;" : "=f"(lo), "=f"(hi) : "l"(v));
    return lo + hi;
}
__device__ __forceinline__ void fma2(u64& d, u64 a, u64 b) {
    asm("fma.rn.f32x2 %0, %1, %2, %0;" : "+l"(d) : "l"(a), "l"(b));
}
__device__ __forceinline__ float sigm(float v) {
    return __fdividef(1.f, 1.f + __expf(-v));
}
__device__ __forceinline__ float tanh_fast(float v) {
    return 1.f - 2.f * __fdividef(1.f, __expf(2.f * v) + 1.f);
}
__device__ __forceinline__ void team_bar(int id) {
    asm volatile("bar.sync %0, 128;" :: "r"(id) : "memory");
}

constexpr int X  = 38;
constexpr int XP = 40;
constexpr int H  = 128;
constexpr int G  = 384;
constexpr int GO = G + X;   // 422
constexpr int T  = 128;
constexpr int B  = 2048;
constexpr int BT = 16;
constexpr int NB = B / BT;  // 128 CTAs
constexpr int NT = 256;
constexpr int RR = 8;       // batch rows per thread

__device__ float g_wih_t[(XP / 4) * G * 4];
__device__ float g_dwih_t[(XP / 4) * G * 4];
__device__ float g_gi[B * T * G];

// ----------------------------- K0: pad/transpose Wih -----------------------
__global__ void pad_wih_kernel(const float* __restrict__ ewih,
                               const float* __restrict__ dwih) {
    int i = blockIdx.x * blockDim.x + threadIdx.x;
    if (i < G * XP) {
        int col = i / XP, k = i - col * XP;
        int dst = (k >> 2) * (G * 4) + col * 4 + (k & 3);
        g_wih_t[dst]  = (k < X) ? ewih[col * X + k] : 0.f;
        g_dwih_t[dst] = (k < X) ? dwih[col * X + k] : 0.f;
    }
}

// ------------------- K1: encoder gi precompute GEMM ------------------------
constexpr int K1R = 32;
__global__ void __launch_bounds__(512, 1)
gi_kernel(const float* __restrict__ x, const float* __restrict__ ebih) {
    __shared__ float xs[K1R * XP];
    const int tid = threadIdx.x;
    const int gr0 = blockIdx.x * K1R;

    for (int i = tid; i < K1R * XP; i += 512) {
        int rr = i / XP, k = i - rr * XP;
        xs[i] = (k < X) ? x[(gr0 + rr) * X + k] : 0.f;
    }
    __syncthreads();

    const int rg = tid >> 7;
    const int ct = tid & 127;
    const int r0 = rg << 3;

    u64 acc[8][3];
    #pragma unroll
    for (int i = 0; i < 3; ++i) {
        float bi = ebih[ct + (i << 7)];
        #pragma unroll
        for (int r = 0; r < 8; ++r) acc[r][i] = pk2(bi, 0.f);
    }
    #pragma unroll
    for (int kb = 0; kb < XP / 4; ++kb) {
        int k = kb << 2;
        ulonglong2 xv[8];
        #pragma unroll
        for (int r = 0; r < 8; ++r)
            xv[r] = *(const ulonglong2*)(xs + (r0 + r) * XP + k);
        #pragma unroll
        for (int i = 0; i < 3; ++i) {
            ulonglong2 wv = *(const ulonglong2*)(g_wih_t + kb * (G * 4) + (ct + (i << 7)) * 4);
            #pragma unroll
            for (int r = 0; r < 8; ++r) {
                fma2(acc[r][i], xv[r].x, wv.x);
                fma2(acc[r][i], xv[r].y, wv.y);
            }
        }
    }
    #pragma unroll
    for (int r = 0; r < 8; ++r) {
        int gr = gr0 + r0 + r;
        int b = gr >> 7, t = gr & (T - 1);
        int blk = b >> 4, lb = b & 15;
        int base = ((blk * T + t) * BT + lb) * G;
        #pragma unroll
        for (int i = 0; i < 3; ++i) g_gi[base + ct + (i << 7)] = red2(acc[r][i]);
    }
}

// ------------------- K2: fused encoder+decoder recurrence ------------------
// enc layout: Ws[384*128] | hA[16*128] | hB[16*128]          = 212992 B
// dec layout: Ws[422*128] | hS[16*128] | oS[16*40]           = 226816 B
constexpr int FUSED_SMB = (GO * H + BT * H + BT * XP) * 4;   // 226816

__global__ void __launch_bounds__(NT, 1)
rae_fused(const float* __restrict__ eWhh, const float* __restrict__ ebhh,
          const float* __restrict__ dWhh,
          const float* __restrict__ dbih, const float* __restrict__ dbhh,
          const float* __restrict__ linW, const float* __restrict__ linb,
          float* __restrict__ out) {
    extern __shared__ float sm[];

    const int tid = threadIdx.x;
    const int tm  = tid >> 7;         // team 0/1
    const int ct  = tid & 127;
    const int r0  = tm << 3;          // 8 rows per team
    const int swz = (ct & 31) << 2;
    const int blk = blockIdx.x;
    const int bid = tm + 1;

    // =========================== ENCODER ===========================
    {
        float* Ws = sm;
        float* hA = Ws + G * H;
        float* hB = hA + BT * H;

        for (int i = tid; i < G * H; i += NT) {
            int c = i >> 7, k = i & 127;
            Ws[(c << 7) + (k ^ ((c & 31) << 2))] = eWhh[i];
        }
        for (int i = tid; i < BT * H; i += NT) hA[i] = 0.f;
        float bh[3];
        #pragma unroll
        for (int i = 0; i < 3; ++i) bh[i] = ebhh[ct + (i << 7)];
        __syncthreads();

        float* hR = hA;
        float* hW = hB;
        float h_own[RR];
        #pragma unroll
        for (int r = 0; r < RR; ++r) h_own[r] = 0.f;

        for (int t = 0; t < T; ++t) {
            float gv[RR][3];
            int gbase = (blk * T + t) * BT * G;
            #pragma unroll
            for (int r = 0; r < RR; ++r)
                #pragma unroll
                for (int i = 0; i < 3; ++i)
                    gv[r][i] = __ldg(&g_gi[gbase + (r0 + r) * G + ct + (i << 7)]);

            u64 aH[RR][3];
            #pragma unroll
            for (int r = 0; r < RR; ++r)
                #pragma unroll
                for (int i = 0; i < 3; ++i) aH[r][i] = pk2(bh[i], 0.f);

            #pragma unroll 4
            for (int kb = 0; kb < H / 4; ++kb) {
                int k = kb << 2;
                ulonglong2 hv[RR];
                #pragma unroll
                for (int r = 0; r < RR; ++r)
                    hv[r] = *(const ulonglong2*)(hR + (r0 + r) * H + k);
                #pragma unroll
                for (int i = 0; i < 3; ++i) {
                    ulonglong2 wv = *(const ulonglong2*)(Ws + ((ct + (i << 7)) << 7) + (k ^ swz));
                    #pragma unroll
                    for (int r = 0; r < RR; ++r) {
                        fma2(aH[r][i], hv[r].x, wv.x);
                        fma2(aH[r][i], hv[r].y, wv.y);
                    }
                }
            }

            #pragma unroll
            for (int r = 0; r < RR; ++r) {
                float rr = sigm(gv[r][0] + red2(aH[r][0]));
                float zz = sigm(gv[r][1] + red2(aH[r][1]));
                float nn = tanh_fast(gv[r][2] + rr * red2(aH[r][2]));
                float hn = (1.f - zz) * nn + zz * h_own[r];
                h_own[r] = hn;
                hW[(r0 + r) * H + ct] = hn;
            }
            team_bar(bid);
            float* tmp = hR; hR = hW; hW = tmp;
        }
        // T even -> final h is in hA; park it in registers for the transition
    }

    __syncthreads();
    float hsave[RR];
    {
        float* hA = sm + G * H;
        #pragma unroll
        for (int i = 0; i < RR; ++i) hsave[i] = hA[tid + NT * i];
    }
    __syncthreads();

    // =========================== DECODER ===========================
    {
        float* Ws = sm;
        float* hS = Ws + GO * H;
        float* oS = hS + BT * H;

        for (int i = tid; i < GO * H; i += NT) {
            int c = i >> 7, k = i & 127;
            float v = (c < G) ? dWhh[i] : linW[(c - G) * H + k];
            Ws[(c << 7) + (k ^ ((c & 31) << 2))] = v;
        }
        __syncthreads();   // weights staged before h restore (regions overlap old hA/hB)
        #pragma unroll
        for (int i = 0; i < RR; ++i) hS[tid + NT * i] = hsave[i];
        for (int i = tid; i < BT * XP; i += NT) oS[i] = 0.f;   // GO = 0
        float bh[3], bi[3];
        #pragma unroll
        for (int i = 0; i < 3; ++i) { bh[i] = dbhh[ct + (i << 7)]; bi[i] = dbih[ct + (i << 7)]; }
        const bool oc = (ct < X);
        const float lb = oc ? linb[ct] : 0.f;
        __syncthreads();

        float h_own[RR];
        #pragma unroll
        for (int r = 0; r < RR; ++r) h_own[r] = hS[(r0 + r) * H + ct];

        // iter t: GEMM(h_{t-1}) -> gh gates + o_{t-1}=lin(h_{t-1})=out[t-1];
        // gi from o_{t-1}; update h. iter t==T only emits out[T-1].
        for (int t = 0; t <= T; ++t) {
            u64 aH[RR][3];
            u64 aL[RR];
            #pragma unroll
            for (int r = 0; r < RR; ++r) {
                #pragma unroll
                for (int i = 0; i < 3; ++i) aH[r][i] = pk2(bh[i], 0.f);
                aL[r] = pk2(lb, 0.f);
            }
            #pragma unroll 4
            for (int kb = 0; kb < H / 4; ++kb) {
                int k = kb << 2;
                ulonglong2 hv[RR];
                #pragma unroll
                for (int r = 0; r < RR; ++r)
                    hv[r] = *(const ulonglong2*)(hS + (r0 + r) * H + k);
                #pragma unroll
                for (int i = 0; i < 3; ++i) {
                    ulonglong2 wv = *(const ulonglong2*)(Ws + ((ct + (i << 7)) << 7) + (k ^ swz));
                    #pragma unroll
                    for (int r = 0; r < RR; ++r) {
                        fma2(aH[r][i], hv[r].x, wv.x);
                        fma2(aH[r][i], hv[r].y, wv.y);
                    }
                }
                if (oc) {
                    ulonglong2 wl = *(const ulonglong2*)(Ws + ((G + ct) << 7) + (k ^ swz));
                    #pragma unroll
                    for (int r = 0; r < RR; ++r) {
                        fma2(aL[r], hv[r].x, wl.x);
                        fma2(aL[r], hv[r].y, wl.y);
                    }
                }
            }
            float gh0[RR], gh1[RR], gh2[RR];
            #pragma unroll
            for (int r = 0; r < RR; ++r) {
                gh0[r] = red2(aH[r][0]); gh1[r] = red2(aH[r][1]); gh2[r] = red2(aH[r][2]);
            }
            if (oc && t > 0) {
                #pragma unroll
                for (int r = 0; r < RR; ++r) {
                    float ov = red2(aL[r]);
                    oS[(r0 + r) * XP + ct] = ov;
                    out[((blk * BT + r0 + r) * T + (t - 1)) * X + ct] = ov;
                }
            }
            if (t == T) break;
            team_bar(bid);   // oS published, hS reads complete (team-local)

            // gi = o_prev @ dWih^T + dbih  (coalesced transposed weights, hot L2)
            u64 aI[RR][3];
            #pragma unroll
            for (int r = 0; r < RR; ++r)
                #pragma unroll
                for (int i = 0; i < 3; ++i) aI[r][i] = pk2(bi[i], 0.f);
            #pragma unroll
            for (int kb = 0; kb < XP / 4; ++kb) {
                int k = kb << 2;
                ulonglong2 xv[RR];
                #pragma unroll
                for (int r = 0; r < RR; ++r)
                    xv[r] = *(const ulonglong2*)(oS + (r0 + r) * XP + k);
                #pragma unroll
                for (int i = 0; i < 3; ++i) {
                    ulonglong2 wv = *(const ulonglong2*)(g_dwih_t + kb * (G * 4) + (ct + (i << 7)) * 4);
                    #pragma unroll
                    for (int r = 0; r < RR; ++r) {
                        fma2(aI[r][i], xv[r].x, wv.x);
                        fma2(aI[r][i], xv[r].y, wv.y);
                    }
                }
            }

            #pragma unroll
            for (int r = 0; r < RR; ++r) {
                float rr = sigm(red2(aI[r][0]) + gh0[r]);
                float zz = sigm(red2(aI[r][1]) + gh1[r]);
                float nn = tanh_fast(red2(aI[r][2]) + rr * gh2[r]);
                float hn = (1.f - zz) * nn + zz * h_own[r];
                h_own[r] = hn;
                hS[(r0 + r) * H + ct] = hn;
            }
            team_bar(bid);   // h updated (team-local)
        }
    }
}

extern "C" void kernel_launch(void* const* d_in, const int* in_sizes, int n_in,
                              void* d_out, int out_size) {
    const float* x    = (const float*)d_in[0];
    const float* eWih = (const float*)d_in[1];
    const float* eWhh = (const float*)d_in[2];
    const float* ebih = (const float*)d_in[3];
    const float* ebhh = (const float*)d_in[4];
    const float* dWih = (const float*)d_in[5];
    const float* dWhh = (const float*)d_in[6];
    const float* dbih = (const float*)d_in[7];
    const float* dbhh = (const float*)d_in[8];
    const float* linW = (const float*)d_in[9];
    const float* linb = (const float*)d_in[10];
    float* out = (float*)d_out;

    pad_wih_kernel<<<(G * XP + 255) / 256, 256>>>(eWih, dWih);
    gi_kernel<<<(B * T) / K1R, 512>>>(x, ebih);

    cudaFuncSetAttribute(rae_fused, cudaFuncAttributeMaxDynamicSharedMemorySize, FUSED_SMB);
    rae_fused<<<NB, NT, FUSED_SMB>>>(eWhh, ebhh, dWhh, dbih, dbhh, linW, linb, out);
}

// round 13
// speedup vs baseline: 1.0659x; 1.0659x over previous
#include <cuda_runtime.h>

// RAE GRU enc-dec. K0: pad+transpose Wih. K1: precompute all encoder gi.
// K2/K3 (split, R11-proven): 256 thr/CTA, 8 batch rows/thread, 2 teams,
// named team barriers, MUFU gates. R13 adds: own-h registers, and decoder
// team-1 column reversal so lin-fold warps spread across SMSPs.

typedef unsigned long long u64;

__device__ __forceinline__ u64 pk2(float lo, float hi) {
    u64 r; asm("mov.b64 %0, {%1,%2};" : "=l"(r) : "f"(lo), "f"(hi)); return r;
}
__device__ __forceinline__ float red2(u64 v) {
    float lo, hi; asm("mov.b64 {%0,%1}, %2;" : "=f"(lo), "=f"(hi) : "l"(v));
    return lo + hi;
}
__device__ __forceinline__ void fma2(u64& d, u64 a, u64 b) {
    asm("fma.rn.f32x2 %0, %1, %2, %0;" : "+l"(d) : "l"(a), "l"(b));
}
__device__ __forceinline__ float sigm(float v) {
    return __fdividef(1.f, 1.f + __expf(-v));
}
__device__ __forceinline__ float tanh_fast(float v) {
    return 1.f - 2.f * __fdividef(1.f, __expf(2.f * v) + 1.f);
}
__device__ __forceinline__ void team_bar(int id) {
    asm volatile("bar.sync %0, 128;" :: "r"(id) : "memory");
}

constexpr int X  = 38;
constexpr int XP = 40;
constexpr int H  = 128;
constexpr int G  = 384;
constexpr int GO = G + X;   // 422
constexpr int T  = 128;
constexpr int B  = 2048;
constexpr int BT = 16;
constexpr int NB = B / BT;  // 128 CTAs
constexpr int NT = 256;
constexpr int RR = 8;       // batch rows per thread

__device__ float g_wih_t[(XP / 4) * G * 4];
__device__ float g_dwih_t[(XP / 4) * G * 4];
__device__ float g_henc[B * H];
__device__ float g_gi[B * T * G];

// ----------------------------- K0: pad/transpose Wih -----------------------
__global__ void pad_wih_kernel(const float* __restrict__ ewih,
                               const float* __restrict__ dwih) {
    int i = blockIdx.x * blockDim.x + threadIdx.x;
    if (i < G * XP) {
        int col = i / XP, k = i - col * XP;
        int dst = (k >> 2) * (G * 4) + col * 4 + (k & 3);
        g_wih_t[dst]  = (k < X) ? ewih[col * X + k] : 0.f;
        g_dwih_t[dst] = (k < X) ? dwih[col * X + k] : 0.f;
    }
}

// ------------------- K1: encoder gi precompute GEMM ------------------------
constexpr int K1R = 32;
__global__ void __launch_bounds__(512, 1)
gi_kernel(const float* __restrict__ x, const float* __restrict__ ebih) {
    __shared__ float xs[K1R * XP];
    const int tid = threadIdx.x;
    const int gr0 = blockIdx.x * K1R;

    for (int i = tid; i < K1R * XP; i += 512) {
        int rr = i / XP, k = i - rr * XP;
        xs[i] = (k < X) ? x[(gr0 + rr) * X + k] : 0.f;
    }
    __syncthreads();

    const int rg = tid >> 7;
    const int ct = tid & 127;
    const int r0 = rg << 3;

    u64 acc[8][3];
    #pragma unroll
    for (int i = 0; i < 3; ++i) {
        float bi = ebih[ct + (i << 7)];
        #pragma unroll
        for (int r = 0; r < 8; ++r) acc[r][i] = pk2(bi, 0.f);
    }
    #pragma unroll
    for (int kb = 0; kb < XP / 4; ++kb) {
        int k = kb << 2;
        ulonglong2 xv[8];
        #pragma unroll
        for (int r = 0; r < 8; ++r)
            xv[r] = *(const ulonglong2*)(xs + (r0 + r) * XP + k);
        #pragma unroll
        for (int i = 0; i < 3; ++i) {
            ulonglong2 wv = *(const ulonglong2*)(g_wih_t + kb * (G * 4) + (ct + (i << 7)) * 4);
            #pragma unroll
            for (int r = 0; r < 8; ++r) {
                fma2(acc[r][i], xv[r].x, wv.x);
                fma2(acc[r][i], xv[r].y, wv.y);
            }
        }
    }
    #pragma unroll
    for (int r = 0; r < 8; ++r) {
        int gr = gr0 + r0 + r;
        int b = gr >> 7, t = gr & (T - 1);
        int blk = b >> 4, lb = b & 15;
        int base = ((blk * T + t) * BT + lb) * G;
        #pragma unroll
        for (int i = 0; i < 3; ++i) g_gi[base + ct + (i << 7)] = red2(acc[r][i]);
    }
}

// ------------------------- K2: encoder recurrence --------------------------
constexpr int ENC_SMB = (G * H + 2 * BT * H) * 4;   // 212992 B

__global__ void __launch_bounds__(NT, 1)
enc_kernel(const float* __restrict__ eWhh, const float* __restrict__ ebhh) {
    extern __shared__ float sm[];
    float* Ws = sm;
    float* hA = Ws + G * H;
    float* hB = hA + BT * H;

    const int tid = threadIdx.x;
    const int tm  = tid >> 7;         // team 0/1
    const int ct  = tid & 127;
    const int r0  = tm << 3;          // 8 rows per team
    const int swz = (ct & 31) << 2;
    const int blk = blockIdx.x;
    const int bid = tm + 1;

    for (int i = tid; i < G * H; i += NT) {
        int c = i >> 7, k = i & 127;
        Ws[(c << 7) + (k ^ ((c & 31) << 2))] = eWhh[i];
    }
    for (int i = tid; i < BT * H; i += NT) hA[i] = 0.f;
    float bh[3];
    #pragma unroll
    for (int i = 0; i < 3; ++i) bh[i] = ebhh[ct + (i << 7)];
    __syncthreads();

    float* hR = hA;
    float* hW = hB;
    float h_own[RR];
    #pragma unroll
    for (int r = 0; r < RR; ++r) h_own[r] = 0.f;

    for (int t = 0; t < T; ++t) {
        // dependency-free gi prefetch (covered by the gh GEMM)
        float gv[RR][3];
        int gbase = (blk * T + t) * BT * G;
        #pragma unroll
        for (int r = 0; r < RR; ++r)
            #pragma unroll
            for (int i = 0; i < 3; ++i)
                gv[r][i] = __ldg(&g_gi[gbase + (r0 + r) * G + ct + (i << 7)]);

        u64 aH[RR][3];
        #pragma unroll
        for (int r = 0; r < RR; ++r)
            #pragma unroll
            for (int i = 0; i < 3; ++i) aH[r][i] = pk2(bh[i], 0.f);

        #pragma unroll 4
        for (int kb = 0; kb < H / 4; ++kb) {
            int k = kb << 2;
            ulonglong2 hv[RR];
            #pragma unroll
            for (int r = 0; r < RR; ++r)
                hv[r] = *(const ulonglong2*)(hR + (r0 + r) * H + k);
            #pragma unroll
            for (int i = 0; i < 3; ++i) {
                ulonglong2 wv = *(const ulonglong2*)(Ws + ((ct + (i << 7)) << 7) + (k ^ swz));
                #pragma unroll
                for (int r = 0; r < RR; ++r) {
                    fma2(aH[r][i], hv[r].x, wv.x);
                    fma2(aH[r][i], hv[r].y, wv.y);
                }
            }
        }

        #pragma unroll
        for (int r = 0; r < RR; ++r) {
            float rr = sigm(gv[r][0] + red2(aH[r][0]));
            float zz = sigm(gv[r][1] + red2(aH[r][1]));
            float nn = tanh_fast(gv[r][2] + rr * red2(aH[r][2]));
            float hn = (1.f - zz) * nn + zz * h_own[r];
            h_own[r] = hn;
            hW[(r0 + r) * H + ct] = hn;
        }
        team_bar(bid);
        float* tmp = hR; hR = hW; hW = tmp;
    }
    __syncthreads();
    for (int i = tid; i < BT * H; i += NT) g_henc[blk * BT * H + i] = hR[i];
}

// ------------------------- K3: decoder recurrence --------------------------
constexpr int DEC_SMB = (GO * H + BT * H + BT * XP) * 4;  // 226816 B

__global__ void __launch_bounds__(NT, 1)
dec_kernel(const float* __restrict__ dWhh,
           const float* __restrict__ dbih, const float* __restrict__ dbhh,
           const float* __restrict__ linW, const float* __restrict__ linb,
           float* __restrict__ out) {
    extern __shared__ float sm[];
    float* Ws = sm;
    float* hS = Ws + GO * H;
    float* oS = hS + BT * H;

    const int tid = threadIdx.x;
    const int tm  = tid >> 7;
    const int ctl = tid & 127;
    // team 1 uses reversed column order: its lin-fold (ct<38) warps land on
    // SMSP 3/2 instead of stacking on SMSP 0/1 with team 0's -> SMSP balance
    const int ct  = tm ? (127 - ctl) : ctl;
    const int r0  = tm << 3;
    const int swz = (ct & 31) << 2;
    const int blk = blockIdx.x;
    const int bid = tm + 1;
    const bool oc = (ct < X);

    for (int i = tid; i < GO * H; i += NT) {
        int c = i >> 7, k = i & 127;
        float v = (c < G) ? dWhh[i] : linW[(c - G) * H + k];
        Ws[(c << 7) + (k ^ ((c & 31) << 2))] = v;
    }
    for (int i = tid; i < BT * H; i += NT) hS[i] = g_henc[blk * BT * H + i];
    for (int i = tid; i < BT * XP; i += NT) oS[i] = 0.f;   // GO = 0
    float bh[3], bi[3];
    #pragma unroll
    for (int i = 0; i < 3; ++i) { bh[i] = dbhh[ct + (i << 7)]; bi[i] = dbih[ct + (i << 7)]; }
    const float lb = oc ? linb[ct] : 0.f;
    __syncthreads();

    float h_own[RR];
    #pragma unroll
    for (int r = 0; r < RR; ++r) h_own[r] = hS[(r0 + r) * H + ct];

    // iter t: GEMM(h_{t-1}) -> gh gates + o_{t-1}=lin(h_{t-1})=out[t-1];
    // gi from o_{t-1}; update h. iter t==T only emits out[T-1].
    for (int t = 0; t <= T; ++t) {
        u64 aH[RR][3];
        u64 aL[RR];
        #pragma unroll
        for (int r = 0; r < RR; ++r) {
            #pragma unroll
            for (int i = 0; i < 3; ++i) aH[r][i] = pk2(bh[i], 0.f);
            aL[r] = pk2(lb, 0.f);
        }
        #pragma unroll 4
        for (int kb = 0; kb < H / 4; ++kb) {
            int k = kb << 2;
            ulonglong2 hv[RR];
            #pragma unroll
            for (int r = 0; r < RR; ++r)
                hv[r] = *(const ulonglong2*)(hS + (r0 + r) * H + k);
            #pragma unroll
            for (int i = 0; i < 3; ++i) {
                ulonglong2 wv = *(const ulonglong2*)(Ws + ((ct + (i << 7)) << 7) + (k ^ swz));
                #pragma unroll
                for (int r = 0; r < RR; ++r) {
                    fma2(aH[r][i], hv[r].x, wv.x);
                    fma2(aH[r][i], hv[r].y, wv.y);
                }
            }
            if (oc) {
                ulonglong2 wl = *(const ulonglong2*)(Ws + ((G + ct) << 7) + (k ^ swz));
                #pragma unroll
                for (int r = 0; r < RR; ++r) {
                    fma2(aL[r], hv[r].x, wl.x);
                    fma2(aL[r], hv[r].y, wl.y);
                }
            }
        }
        float gh0[RR], gh1[RR], gh2[RR];
        #pragma unroll
        for (int r = 0; r < RR; ++r) {
            gh0[r] = red2(aH[r][0]); gh1[r] = red2(aH[r][1]); gh2[r] = red2(aH[r][2]);
        }
        if (oc && t > 0) {
            #pragma unroll
            for (int r = 0; r < RR; ++r) {
                float ov = red2(aL[r]);
                oS[(r0 + r) * XP + ct] = ov;
                out[((blk * BT + r0 + r) * T + (t - 1)) * X + ct] = ov;
            }
        }
        if (t == T) break;
        team_bar(bid);   // oS published, hS reads complete (team-local)

        // gi = o_prev @ dWih^T + dbih  (coalesced transposed weights, hot L2)
        u64 aI[RR][3];
        #pragma unroll
        for (int r = 0; r < RR; ++r)
            #pragma unroll
            for (int i = 0; i < 3; ++i) aI[r][i] = pk2(bi[i], 0.f);
        #pragma unroll
        for (int kb = 0; kb < XP / 4; ++kb) {
            int k = kb << 2;
            ulonglong2 xv[RR];
            #pragma unroll
            for (int r = 0; r < RR; ++r)
                xv[r] = *(const ulonglong2*)(oS + (r0 + r) * XP + k);
            #pragma unroll
            for (int i = 0; i < 3; ++i) {
                ulonglong2 wv = *(const ulonglong2*)(g_dwih_t + kb * (G * 4) + (ct + (i << 7)) * 4);
                #pragma unroll
                for (int r = 0; r < RR; ++r) {
                    fma2(aI[r][i], xv[r].x, wv.x);
                    fma2(aI[r][i], xv[r].y, wv.y);
                }
            }
        }

        #pragma unroll
        for (int r = 0; r < RR; ++r) {
            float rr = sigm(red2(aI[r][0]) + gh0[r]);
            float zz = sigm(red2(aI[r][1]) + gh1[r]);
            float nn = tanh_fast(red2(aI[r][2]) + rr * gh2[r]);
            float hn = (1.f - zz) * nn + zz * h_own[r];
            h_own[r] = hn;
            hS[(r0 + r) * H + ct] = hn;
        }
        team_bar(bid);   // h updated (team-local)
    }
}

extern "C" void kernel_launch(void* const* d_in, const int* in_sizes, int n_in,
                              void* d_out, int out_size) {
    const float* x    = (const float*)d_in[0];
    const float* eWih = (const float*)d_in[1];
    const float* eWhh = (const float*)d_in[2];
    const float* ebih = (const float*)d_in[3];
    const float* ebhh = (const float*)d_in[4];
    const float* dWih = (const float*)d_in[5];
    const float* dWhh = (const float*)d_in[6];
    const float* dbih = (const float*)d_in[7];
    const float* dbhh = (const float*)d_in[8];
    const float* linW = (const float*)d_in[9];
    const float* linb = (const float*)d_in[10];
    float* out = (float*)d_out;

    pad_wih_kernel<<<(G * XP + 255) / 256, 256>>>(eWih, dWih);
    gi_kernel<<<(B * T) / K1R, 512>>>(x, ebih);

    cudaFuncSetAttribute(enc_kernel, cudaFuncAttributeMaxDynamicSharedMemorySize, ENC_SMB);
    enc_kernel<<<NB, NT, ENC_SMB>>>(eWhh, ebhh);

    cudaFuncSetAttribute(dec_kernel, cudaFuncAttributeMaxDynamicSharedMemorySize, DEC_SMB);
    dec_kernel<<<NB, NT, DEC_SMB>>>(dWhh, dbih, dbhh, linW, linb, out);
}

// round 14
// speedup vs baseline: 1.0797x; 1.0129x over previous
#include <cuda_runtime.h>
#include <cuda_fp16.h>

// RAE GRU enc-dec. K0: pad+transpose Wih. K1: precompute all encoder gi (fp16).
// K2/K3: 256 thr/CTA, 8 batch rows/thread, 2 teams, named team barriers,
// MUFU gates, own-h registers, decoder team-1 column reversal (SMSP balance).

typedef unsigned long long u64;

__device__ __forceinline__ u64 pk2(float lo, float hi) {
    u64 r; asm("mov.b64 %0, {%1,%2};" : "=l"(r) : "f"(lo), "f"(hi)); return r;
}
__device__ __forceinline__ float red2(u64 v) {
    float lo, hi; asm("mov.b64 {%0,%1}, %2;" : "=f"(lo), "=f"(hi) : "l"(v));
    return lo + hi;
}
__device__ __forceinline__ void fma2(u64& d, u64 a, u64 b) {
    asm("fma.rn.f32x2 %0, %1, %2, %0;" : "+l"(d) : "l"(a), "l"(b));
}
__device__ __forceinline__ float sigm(float v) {
    return __fdividef(1.f, 1.f + __expf(-v));
}
__device__ __forceinline__ float tanh_fast(float v) {
    return 1.f - 2.f * __fdividef(1.f, __expf(2.f * v) + 1.f);
}
__device__ __forceinline__ void team_bar(int id) {
    asm volatile("bar.sync %0, 128;" :: "r"(id) : "memory");
}

constexpr int X  = 38;
constexpr int XP = 40;
constexpr int H  = 128;
constexpr int G  = 384;
constexpr int GO = G + X;   // 422
constexpr int T  = 128;
constexpr int B  = 2048;
constexpr int BT = 16;
constexpr int NB = B / BT;  // 128 CTAs
constexpr int NT = 256;
constexpr int RR = 8;       // batch rows per thread

__device__ float  g_wih_t[(XP / 4) * G * 4];
__device__ float  g_dwih_t[(XP / 4) * G * 4];
__device__ float  g_henc[B * H];
__device__ __half g_gi[B * T * G];   // fp16: halves the gi DRAM roundtrip

// ----------------------------- K0: pad/transpose Wih -----------------------
__global__ void pad_wih_kernel(const float* __restrict__ ewih,
                               const float* __restrict__ dwih) {
    int i = blockIdx.x * blockDim.x + threadIdx.x;
    if (i < G * XP) {
        int col = i / XP, k = i - col * XP;
        int dst = (k >> 2) * (G * 4) + col * 4 + (k & 3);
        g_wih_t[dst]  = (k < X) ? ewih[col * X + k] : 0.f;
        g_dwih_t[dst] = (k < X) ? dwih[col * X + k] : 0.f;
    }
}

// ------------------- K1: encoder gi precompute GEMM ------------------------
constexpr int K1R = 32;
__global__ void __launch_bounds__(512, 1)
gi_kernel(const float* __restrict__ x, const float* __restrict__ ebih) {
    __shared__ float xs[K1R * XP];
    const int tid = threadIdx.x;
    const int gr0 = blockIdx.x * K1R;

    for (int i = tid; i < K1R * XP; i += 512) {
        int rr = i / XP, k = i - rr * XP;
        xs[i] = (k < X) ? x[(gr0 + rr) * X + k] : 0.f;
    }
    __syncthreads();

    const int rg = tid >> 7;
    const int ct = tid & 127;
    const int r0 = rg << 3;

    u64 acc[8][3];
    #pragma unroll
    for (int i = 0; i < 3; ++i) {
        float bi = ebih[ct + (i << 7)];
        #pragma unroll
        for (int r = 0; r < 8; ++r) acc[r][i] = pk2(bi, 0.f);
    }
    #pragma unroll
    for (int kb = 0; kb < XP / 4; ++kb) {
        int k = kb << 2;
        ulonglong2 xv[8];
        #pragma unroll
        for (int r = 0; r < 8; ++r)
            xv[r] = *(const ulonglong2*)(xs + (r0 + r) * XP + k);
        #pragma unroll
        for (int i = 0; i < 3; ++i) {
            ulonglong2 wv = *(const ulonglong2*)(g_wih_t + kb * (G * 4) + (ct + (i << 7)) * 4);
            #pragma unroll
            for (int r = 0; r < 8; ++r) {
                fma2(acc[r][i], xv[r].x, wv.x);
                fma2(acc[r][i], xv[r].y, wv.y);
            }
        }
    }
    #pragma unroll
    for (int r = 0; r < 8; ++r) {
        int gr = gr0 + r0 + r;
        int b = gr >> 7, t = gr & (T - 1);
        int blk = b >> 4, lb = b & 15;
        int base = ((blk * T + t) * BT + lb) * G;
        #pragma unroll
        for (int i = 0; i < 3; ++i)
            g_gi[base + ct + (i << 7)] = __float2half(red2(acc[r][i]));
    }
}

// ------------------------- K2: encoder recurrence --------------------------
constexpr int ENC_SMB = (G * H + 2 * BT * H) * 4;   // 212992 B

__global__ void __launch_bounds__(NT, 1)
enc_kernel(const float* __restrict__ eWhh, const float* __restrict__ ebhh) {
    extern __shared__ float sm[];
    float* Ws = sm;
    float* hA = Ws + G * H;
    float* hB = hA + BT * H;

    const int tid = threadIdx.x;
    const int tm  = tid >> 7;         // team 0/1
    const int ct  = tid & 127;
    const int r0  = tm << 3;          // 8 rows per team
    const int swz = (ct & 31) << 2;
    const int blk = blockIdx.x;
    const int bid = tm + 1;

    for (int i = tid; i < G * H; i += NT) {
        int c = i >> 7, k = i & 127;
        Ws[(c << 7) + (k ^ ((c & 31) << 2))] = eWhh[i];
    }
    for (int i = tid; i < BT * H; i += NT) hA[i] = 0.f;
    float bh[3];
    #pragma unroll
    for (int i = 0; i < 3; ++i) bh[i] = ebhh[ct + (i << 7)];
    __syncthreads();

    float* hR = hA;
    float* hW = hB;
    float h_own[RR];
    #pragma unroll
    for (int r = 0; r < RR; ++r) h_own[r] = 0.f;

    for (int t = 0; t < T; ++t) {
        // dependency-free gi prefetch (fp16, covered by the gh GEMM)
        __half gv[RR][3];
        int gbase = (blk * T + t) * BT * G;
        #pragma unroll
        for (int r = 0; r < RR; ++r)
            #pragma unroll
            for (int i = 0; i < 3; ++i)
                gv[r][i] = g_gi[gbase + (r0 + r) * G + ct + (i << 7)];

        u64 aH[RR][3];
        #pragma unroll
        for (int r = 0; r < RR; ++r)
            #pragma unroll
            for (int i = 0; i < 3; ++i) aH[r][i] = pk2(bh[i], 0.f);

        #pragma unroll 8
        for (int kb = 0; kb < H / 4; ++kb) {
            int k = kb << 2;
            ulonglong2 hv[RR];
            #pragma unroll
            for (int r = 0; r < RR; ++r)
                hv[r] = *(const ulonglong2*)(hR + (r0 + r) * H + k);
            #pragma unroll
            for (int i = 0; i < 3; ++i) {
                ulonglong2 wv = *(const ulonglong2*)(Ws + ((ct + (i << 7)) << 7) + (k ^ swz));
                #pragma unroll
                for (int r = 0; r < RR; ++r) {
                    fma2(aH[r][i], hv[r].x, wv.x);
                    fma2(aH[r][i], hv[r].y, wv.y);
                }
            }
        }

        #pragma unroll
        for (int r = 0; r < RR; ++r) {
            float rr = sigm(__half2float(gv[r][0]) + red2(aH[r][0]));
            float zz = sigm(__half2float(gv[r][1]) + red2(aH[r][1]));
            float nn = tanh_fast(__half2float(gv[r][2]) + rr * red2(aH[r][2]));
            float hn = (1.f - zz) * nn + zz * h_own[r];
            h_own[r] = hn;
            hW[(r0 + r) * H + ct] = hn;
        }
        team_bar(bid);
        float* tmp = hR; hR = hW; hW = tmp;
    }
    __syncthreads();
    for (int i = tid; i < BT * H; i += NT) g_henc[blk * BT * H + i] = hR[i];
}

// ------------------------- K3: decoder recurrence --------------------------
constexpr int DEC_SMB = (GO * H + BT * H + BT * XP) * 4;  // 226816 B

__global__ void __launch_bounds__(NT, 1)
dec_kernel(const float* __restrict__ dWhh,
           const float* __restrict__ dbih, const float* __restrict__ dbhh,
           const float* __restrict__ linW, const float* __restrict__ linb,
           float* __restrict__ out) {
    extern __shared__ float sm[];
    float* Ws = sm;
    float* hS = Ws + GO * H;
    float* oS = hS + BT * H;

    const int tid = threadIdx.x;
    const int tm  = tid >> 7;
    const int ctl = tid & 127;
    // team 1 reversed column order: its lin-fold (ct<38) warps land on SMSP
    // 3/2 instead of stacking on SMSP 0/1 with team 0's -> SMSP balance
    const int ct  = tm ? (127 - ctl) : ctl;
    const int r0  = tm << 3;
    const int swz = (ct & 31) << 2;
    const int blk = blockIdx.x;
    const int bid = tm + 1;
    const bool oc = (ct < X);

    for (int i = tid; i < GO * H; i += NT) {
        int c = i >> 7, k = i & 127;
        float v = (c < G) ? dWhh[i] : linW[(c - G) * H + k];
        Ws[(c << 7) + (k ^ ((c & 31) << 2))] = v;
    }
    for (int i = tid; i < BT * H; i += NT) hS[i] = g_henc[blk * BT * H + i];
    for (int i = tid; i < BT * XP; i += NT) oS[i] = 0.f;   // GO = 0
    float bh[3], bi[3];
    #pragma unroll
    for (int i = 0; i < 3; ++i) { bh[i] = dbhh[ct + (i << 7)]; bi[i] = dbih[ct + (i << 7)]; }
    const float lb = oc ? linb[ct] : 0.f;
    __syncthreads();

    float h_own[RR];
    #pragma unroll
    for (int r = 0; r < RR; ++r) h_own[r] = hS[(r0 + r) * H + ct];

    // iter t: GEMM(h_{t-1}) -> gh gates + o_{t-1}=lin(h_{t-1})=out[t-1];
    // gi from o_{t-1}; update h. iter t==T only emits out[T-1].
    for (int t = 0; t <= T; ++t) {
        u64 aH[RR][3];
        u64 aL[RR];
        #pragma unroll
        for (int r = 0; r < RR; ++r) {
            #pragma unroll
            for (int i = 0; i < 3; ++i) aH[r][i] = pk2(bh[i], 0.f);
            aL[r] = pk2(lb, 0.f);
        }
        #pragma unroll 4
        for (int kb = 0; kb < H / 4; ++kb) {
            int k = kb << 2;
            ulonglong2 hv[RR];
            #pragma unroll
            for (int r = 0; r < RR; ++r)
                hv[r] = *(const ulonglong2*)(hS + (r0 + r) * H + k);
            #pragma unroll
            for (int i = 0; i < 3; ++i) {
                ulonglong2 wv = *(const ulonglong2*)(Ws + ((ct + (i << 7)) << 7) + (k ^ swz));
                #pragma unroll
                for (int r = 0; r < RR; ++r) {
                    fma2(aH[r][i], hv[r].x, wv.x);
                    fma2(aH[r][i], hv[r].y, wv.y);
                }
            }
            if (oc) {
                ulonglong2 wl = *(const ulonglong2*)(Ws + ((G + ct) << 7) + (k ^ swz));
                #pragma unroll
                for (int r = 0; r < RR; ++r) {
                    fma2(aL[r], hv[r].x, wl.x);
                    fma2(aL[r], hv[r].y, wl.y);
                }
            }
        }
        float gh0[RR], gh1[RR], gh2[RR];
        #pragma unroll
        for (int r = 0; r < RR; ++r) {
            gh0[r] = red2(aH[r][0]); gh1[r] = red2(aH[r][1]); gh2[r] = red2(aH[r][2]);
        }
        if (oc && t > 0) {
            #pragma unroll
            for (int r = 0; r < RR; ++r) {
                float ov = red2(aL[r]);
                oS[(r0 + r) * XP + ct] = ov;
                out[((blk * BT + r0 + r) * T + (t - 1)) * X + ct] = ov;
            }
        }
        if (t == T) break;
        team_bar(bid);   // oS published, hS reads complete (team-local)

        // gi = o_prev @ dWih^T + dbih  (coalesced transposed weights, hot L2)
        u64 aI[RR][3];
        #pragma unroll
        for (int r = 0; r < RR; ++r)
            #pragma unroll
            for (int i = 0; i < 3; ++i) aI[r][i] = pk2(bi[i], 0.f);
        #pragma unroll
        for (int kb = 0; kb < XP / 4; ++kb) {
            int k = kb << 2;
            ulonglong2 xv[RR];
            #pragma unroll
            for (int r = 0; r < RR; ++r)
                xv[r] = *(const ulonglong2*)(oS + (r0 + r) * XP + k);
            #pragma unroll
            for (int i = 0; i < 3; ++i) {
                ulonglong2 wv = *(const ulonglong2*)(g_dwih_t + kb * (G * 4) + (ct + (i << 7)) * 4);
                #pragma unroll
                for (int r = 0; r < RR; ++r) {
                    fma2(aI[r][i], xv[r].x, wv.x);
                    fma2(aI[r][i], xv[r].y, wv.y);
                }
            }
        }

        #pragma unroll
        for (int r = 0; r < RR; ++r) {
            float rr = sigm(red2(aI[r][0]) + gh0[r]);
            float zz = sigm(red2(aI[r][1]) + gh1[r]);
            float nn = tanh_fast(red2(aI[r][2]) + rr * gh2[r]);
            float hn = (1.f - zz) * nn + zz * h_own[r];
            h_own[r] = hn;
            hS[(r0 + r) * H + ct] = hn;
        }
        team_bar(bid);   // h updated (team-local)
    }
}

extern "C" void kernel_launch(void* const* d_in, const int* in_sizes, int n_in,
                              void* d_out, int out_size) {
    const float* x    = (const float*)d_in[0];
    const float* eWih = (const float*)d_in[1];
    const float* eWhh = (const float*)d_in[2];
    const float* ebih = (const float*)d_in[3];
    const float* ebhh = (const float*)d_in[4];
    const float* dWih = (const float*)d_in[5];
    const float* dWhh = (const float*)d_in[6];
    const float* dbih = (const float*)d_in[7];
    const float* dbhh = (const float*)d_in[8];
    const float* linW = (const float*)d_in[9];
    const float* linb = (const float*)d_in[10];
    float* out = (float*)d_out;

    pad_wih_kernel<<<(G * XP + 255) / 256, 256>>>(eWih, dWih);
    gi_kernel<<<(B * T) / K1R, 512>>>(x, ebih);

    cudaFuncSetAttribute(enc_kernel, cudaFuncAttributeMaxDynamicSharedMemorySize, ENC_SMB);
    enc_kernel<<<NB, NT, ENC_SMB>>>(eWhh, ebhh);

    cudaFuncSetAttribute(dec_kernel, cudaFuncAttributeMaxDynamicSharedMemorySize, DEC_SMB);
    dec_kernel<<<NB, NT, DEC_SMB>>>(dWhh, dbih, dbhh, linW, linb, out);
}

// round 15
// speedup vs baseline: 1.0797x; 1.0000x over previous
#include <cuda_runtime.h>
#include <cuda_fp16.h>

// RAE GRU enc-dec. K0: pad+transpose Wih. K1: precompute all encoder gi (fp16).
// K2/K3: 256 thr/CTA, 8 batch rows/thread, 2 teams, named team barriers,
// MUFU gates, own-h registers, decoder team-1 column reversal (SMSP balance).

typedef unsigned long long u64;

__device__ __forceinline__ u64 pk2(float lo, float hi) {
    u64 r; asm("mov.b64 %0, {%1,%2};" : "=l"(r) : "f"(lo), "f"(hi)); return r;
}
__device__ __forceinline__ float red2(u64 v) {
    float lo, hi; asm("mov.b64 {%0,%1}, %2;" : "=f"(lo), "=f"(hi) : "l"(v));
    return lo + hi;
}
__device__ __forceinline__ void fma2(u64& d, u64 a, u64 b) {
    asm("fma.rn.f32x2 %0, %1, %2, %0;" : "+l"(d) : "l"(a), "l"(b));
}
__device__ __forceinline__ float sigm(float v) {
    return __fdividef(1.f, 1.f + __expf(-v));
}
__device__ __forceinline__ float tanh_fast(float v) {
    return 1.f - 2.f * __fdividef(1.f, __expf(2.f * v) + 1.f);
}
__device__ __forceinline__ void team_bar(int id) {
    asm volatile("bar.sync %0, 128;" :: "r"(id) : "memory");
}

constexpr int X  = 38;
constexpr int XP = 40;
constexpr int H  = 128;
constexpr int G  = 384;
constexpr int GO = G + X;   // 422
constexpr int T  = 128;
constexpr int B  = 2048;
constexpr int BT = 16;
constexpr int NB = B / BT;  // 128 CTAs
constexpr int NT = 256;
constexpr int RR = 8;       // batch rows per thread

__device__ float  g_wih_t[(XP / 4) * G * 4];
__device__ float  g_dwih_t[(XP / 4) * G * 4];
__device__ float  g_henc[B * H];
__device__ __half g_gi[B * T * G];   // fp16: halves the gi DRAM roundtrip

// ----------------------------- K0: pad/transpose Wih -----------------------
__global__ void pad_wih_kernel(const float* __restrict__ ewih,
                               const float* __restrict__ dwih) {
    int i = blockIdx.x * blockDim.x + threadIdx.x;
    if (i < G * XP) {
        int col = i / XP, k = i - col * XP;
        int dst = (k >> 2) * (G * 4) + col * 4 + (k & 3);
        g_wih_t[dst]  = (k < X) ? ewih[col * X + k] : 0.f;
        g_dwih_t[dst] = (k < X) ? dwih[col * X + k] : 0.f;
    }
}

// ------------------- K1: encoder gi precompute GEMM ------------------------
constexpr int K1R = 32;
__global__ void __launch_bounds__(512, 1)
gi_kernel(const float* __restrict__ x, const float* __restrict__ ebih) {
    __shared__ float xs[K1R * XP];
    const int tid = threadIdx.x;
    const int gr0 = blockIdx.x * K1R;

    for (int i = tid; i < K1R * XP; i += 512) {
        int rr = i / XP, k = i - rr * XP;
        xs[i] = (k < X) ? x[(gr0 + rr) * X + k] : 0.f;
    }
    __syncthreads();

    const int rg = tid >> 7;
    const int ct = tid & 127;
    const int r0 = rg << 3;

    u64 acc[8][3];
    #pragma unroll
    for (int i = 0; i < 3; ++i) {
        float bi = ebih[ct + (i << 7)];
        #pragma unroll
        for (int r = 0; r < 8; ++r) acc[r][i] = pk2(bi, 0.f);
    }
    #pragma unroll
    for (int kb = 0; kb < XP / 4; ++kb) {
        int k = kb << 2;
        ulonglong2 xv[8];
        #pragma unroll
        for (int r = 0; r < 8; ++r)
            xv[r] = *(const ulonglong2*)(xs + (r0 + r) * XP + k);
        #pragma unroll
        for (int i = 0; i < 3; ++i) {
            ulonglong2 wv = *(const ulonglong2*)(g_wih_t + kb * (G * 4) + (ct + (i << 7)) * 4);
            #pragma unroll
            for (int r = 0; r < 8; ++r) {
                fma2(acc[r][i], xv[r].x, wv.x);
                fma2(acc[r][i], xv[r].y, wv.y);
            }
        }
    }
    #pragma unroll
    for (int r = 0; r < 8; ++r) {
        int gr = gr0 + r0 + r;
        int b = gr >> 7, t = gr & (T - 1);
        int blk = b >> 4, lb = b & 15;
        int base = ((blk * T + t) * BT + lb) * G;
        #pragma unroll
        for (int i = 0; i < 3; ++i)
            g_gi[base + ct + (i << 7)] = __float2half(red2(acc[r][i]));
    }
}

// ------------------------- K2: encoder recurrence --------------------------
constexpr int ENC_SMB = (G * H + 2 * BT * H) * 4;   // 212992 B

__global__ void __launch_bounds__(NT, 1)
enc_kernel(const float* __restrict__ eWhh, const float* __restrict__ ebhh) {
    extern __shared__ float sm[];
    float* Ws = sm;
    float* hA = Ws + G * H;
    float* hB = hA + BT * H;

    const int tid = threadIdx.x;
    const int tm  = tid >> 7;         // team 0/1
    const int ct  = tid & 127;
    const int r0  = tm << 3;          // 8 rows per team
    const int swz = (ct & 31) << 2;
    const int blk = blockIdx.x;
    const int bid = tm + 1;

    for (int i = tid; i < G * H; i += NT) {
        int c = i >> 7, k = i & 127;
        Ws[(c << 7) + (k ^ ((c & 31) << 2))] = eWhh[i];
    }
    for (int i = tid; i < BT * H; i += NT) hA[i] = 0.f;
    float bh[3];
    #pragma unroll
    for (int i = 0; i < 3; ++i) bh[i] = ebhh[ct + (i << 7)];
    __syncthreads();

    float* hR = hA;
    float* hW = hB;
    float h_own[RR];
    #pragma unroll
    for (int r = 0; r < RR; ++r) h_own[r] = 0.f;

    for (int t = 0; t < T; ++t) {
        // dependency-free gi prefetch (fp16, covered by the gh GEMM)
        __half gv[RR][3];
        int gbase = (blk * T + t) * BT * G;
        #pragma unroll
        for (int r = 0; r < RR; ++r)
            #pragma unroll
            for (int i = 0; i < 3; ++i)
                gv[r][i] = g_gi[gbase + (r0 + r) * G + ct + (i << 7)];

        u64 aH[RR][3];
        #pragma unroll
        for (int r = 0; r < RR; ++r)
            #pragma unroll
            for (int i = 0; i < 3; ++i) aH[r][i] = pk2(bh[i], 0.f);

        #pragma unroll 8
        for (int kb = 0; kb < H / 4; ++kb) {
            int k = kb << 2;
            ulonglong2 hv[RR];
            #pragma unroll
            for (int r = 0; r < RR; ++r)
                hv[r] = *(const ulonglong2*)(hR + (r0 + r) * H + k);
            #pragma unroll
            for (int i = 0; i < 3; ++i) {
                ulonglong2 wv = *(const ulonglong2*)(Ws + ((ct + (i << 7)) << 7) + (k ^ swz));
                #pragma unroll
                for (int r = 0; r < RR; ++r) {
                    fma2(aH[r][i], hv[r].x, wv.x);
                    fma2(aH[r][i], hv[r].y, wv.y);
                }
            }
        }

        #pragma unroll
        for (int r = 0; r < RR; ++r) {
            float rr = sigm(__half2float(gv[r][0]) + red2(aH[r][0]));
            float zz = sigm(__half2float(gv[r][1]) + red2(aH[r][1]));
            float nn = tanh_fast(__half2float(gv[r][2]) + rr * red2(aH[r][2]));
            float hn = (1.f - zz) * nn + zz * h_own[r];
            h_own[r] = hn;
            hW[(r0 + r) * H + ct] = hn;
        }
        team_bar(bid);
        float* tmp = hR; hR = hW; hW = tmp;
    }
    __syncthreads();
    for (int i = tid; i < BT * H; i += NT) g_henc[blk * BT * H + i] = hR[i];
}

// ------------------------- K3: decoder recurrence --------------------------
constexpr int DEC_SMB = (GO * H + BT * H + BT * XP) * 4;  // 226816 B

__global__ void __launch_bounds__(NT, 1)
dec_kernel(const float* __restrict__ dWhh,
           const float* __restrict__ dbih, const float* __restrict__ dbhh,
           const float* __restrict__ linW, const float* __restrict__ linb,
           float* __restrict__ out) {
    extern __shared__ float sm[];
    float* Ws = sm;
    float* hS = Ws + GO * H;
    float* oS = hS + BT * H;

    const int tid = threadIdx.x;
    const int tm  = tid >> 7;
    const int ctl = tid & 127;
    // team 1 reversed column order: its lin-fold (ct<38) warps land on SMSP
    // 3/2 instead of stacking on SMSP 0/1 with team 0's -> SMSP balance
    const int ct  = tm ? (127 - ctl) : ctl;
    const int r0  = tm << 3;
    const int swz = (ct & 31) << 2;
    const int blk = blockIdx.x;
    const int bid = tm + 1;
    const bool oc = (ct < X);

    for (int i = tid; i < GO * H; i += NT) {
        int c = i >> 7, k = i & 127;
        float v = (c < G) ? dWhh[i] : linW[(c - G) * H + k];
        Ws[(c << 7) + (k ^ ((c & 31) << 2))] = v;
    }
    for (int i = tid; i < BT * H; i += NT) hS[i] = g_henc[blk * BT * H + i];
    for (int i = tid; i < BT * XP; i += NT) oS[i] = 0.f;   // GO = 0
    float bh[3], bi[3];
    #pragma unroll
    for (int i = 0; i < 3; ++i) { bh[i] = dbhh[ct + (i << 7)]; bi[i] = dbih[ct + (i << 7)]; }
    const float lb = oc ? linb[ct] : 0.f;
    __syncthreads();

    float h_own[RR];
    #pragma unroll
    for (int r = 0; r < RR; ++r) h_own[r] = hS[(r0 + r) * H + ct];

    // iter t: GEMM(h_{t-1}) -> gh gates + o_{t-1}=lin(h_{t-1})=out[t-1];
    // gi from o_{t-1}; update h. iter t==T only emits out[T-1].
    for (int t = 0; t <= T; ++t) {
        u64 aH[RR][3];
        u64 aL[RR];
        #pragma unroll
        for (int r = 0; r < RR; ++r) {
            #pragma unroll
            for (int i = 0; i < 3; ++i) aH[r][i] = pk2(bh[i], 0.f);
            aL[r] = pk2(lb, 0.f);
        }
        #pragma unroll 4
        for (int kb = 0; kb < H / 4; ++kb) {
            int k = kb << 2;
            ulonglong2 hv[RR];
            #pragma unroll
            for (int r = 0; r < RR; ++r)
                hv[r] = *(const ulonglong2*)(hS + (r0 + r) * H + k);
            #pragma unroll
            for (int i = 0; i < 3; ++i) {
                ulonglong2 wv = *(const ulonglong2*)(Ws + ((ct + (i << 7)) << 7) + (k ^ swz));
                #pragma unroll
                for (int r = 0; r < RR; ++r) {
                    fma2(aH[r][i], hv[r].x, wv.x);
                    fma2(aH[r][i], hv[r].y, wv.y);
                }
            }
            if (oc) {
                ulonglong2 wl = *(const ulonglong2*)(Ws + ((G + ct) << 7) + (k ^ swz));
                #pragma unroll
                for (int r = 0; r < RR; ++r) {
                    fma2(aL[r], hv[r].x, wl.x);
                    fma2(aL[r], hv[r].y, wl.y);
                }
            }
        }
        float gh0[RR], gh1[RR], gh2[RR];
        #pragma unroll
        for (int r = 0; r < RR; ++r) {
            gh0[r] = red2(aH[r][0]); gh1[r] = red2(aH[r][1]); gh2[r] = red2(aH[r][2]);
        }
        if (oc && t > 0) {
            #pragma unroll
            for (int r = 0; r < RR; ++r) {
                float ov = red2(aL[r]);
                oS[(r0 + r) * XP + ct] = ov;
                out[((blk * BT + r0 + r) * T + (t - 1)) * X + ct] = ov;
            }
        }
        if (t == T) break;
        team_bar(bid);   // oS published, hS reads complete (team-local)

        // gi = o_prev @ dWih^T + dbih  (coalesced transposed weights, hot L2)
        u64 aI[RR][3];
        #pragma unroll
        for (int r = 0; r < RR; ++r)
            #pragma unroll
            for (int i = 0; i < 3; ++i) aI[r][i] = pk2(bi[i], 0.f);
        #pragma unroll
        for (int kb = 0; kb < XP / 4; ++kb) {
            int k = kb << 2;
            ulonglong2 xv[RR];
            #pragma unroll
            for (int r = 0; r < RR; ++r)
                xv[r] = *(const ulonglong2*)(oS + (r0 + r) * XP + k);
            #pragma unroll
            for (int i = 0; i < 3; ++i) {
                ulonglong2 wv = *(const ulonglong2*)(g_dwih_t + kb * (G * 4) + (ct + (i << 7)) * 4);
                #pragma unroll
                for (int r = 0; r < RR; ++r) {
                    fma2(aI[r][i], xv[r].x, wv.x);
                    fma2(aI[r][i], xv[r].y, wv.y);
                }
            }
        }

        #pragma unroll
        for (int r = 0; r < RR; ++r) {
            float rr = sigm(red2(aI[r][0]) + gh0[r]);
            float zz = sigm(red2(aI[r][1]) + gh1[r]);
            float nn = tanh_fast(red2(aI[r][2]) + rr * gh2[r]);
            float hn = (1.f - zz) * nn + zz * h_own[r];
            h_own[r] = hn;
            hS[(r0 + r) * H + ct] = hn;
        }
        team_bar(bid);   // h updated (team-local)
    }
}

extern "C" void kernel_launch(void* const* d_in, const int* in_sizes, int n_in,
                              void* d_out, int out_size) {
    const float* x    = (const float*)d_in[0];
    const float* eWih = (const float*)d_in[1];
    const float* eWhh = (const float*)d_in[2];
    const float* ebih = (const float*)d_in[3];
    const float* ebhh = (const float*)d_in[4];
    const float* dWih = (const float*)d_in[5];
    const float* dWhh = (const float*)d_in[6];
    const float* dbih = (const float*)d_in[7];
    const float* dbhh = (const float*)d_in[8];
    const float* linW = (const float*)d_in[9];
    const float* linb = (const float*)d_in[10];
    float* out = (float*)d_out;

    pad_wih_kernel<<<(G * XP + 255) / 256, 256>>>(eWih, dWih);
    gi_kernel<<<(B * T) / K1R, 512>>>(x, ebih);

    cudaFuncSetAttribute(enc_kernel, cudaFuncAttributeMaxDynamicSharedMemorySize, ENC_SMB);
    enc_kernel<<<NB, NT, ENC_SMB>>>(eWhh, ebhh);

    cudaFuncSetAttribute(dec_kernel, cudaFuncAttributeMaxDynamicSharedMemorySize, DEC_SMB);
    dec_kernel<<<NB, NT, DEC_SMB>>>(dWhh, dbih, dbhh, linW, linb, out);
}